// round 11
// baseline (speedup 1.0000x reference)
#include <cuda_runtime.h>

typedef unsigned long long u64;

// ---------- packed f32x2 helpers ----------
__device__ __forceinline__ u64 fma2(u64 a, u64 b, u64 c){
    u64 d; asm("fma.rn.f32x2 %0, %1, %2, %3;" : "=l"(d) : "l"(a), "l"(b), "l"(c)); return d;
}
__device__ __forceinline__ u64 mul2(u64 a, u64 b){
    u64 d; asm("mul.rn.f32x2 %0, %1, %2;" : "=l"(d) : "l"(a), "l"(b)); return d;
}
__device__ __forceinline__ u64 pk2(float lo, float hi){
    u64 d; asm("mov.b64 %0, {%1, %2};" : "=l"(d) : "f"(lo), "f"(hi)); return d;
}
__device__ __forceinline__ void upk2(u64 v, float& lo, float& hi){
    asm("mov.b64 {%0, %1}, %2;" : "=f"(lo), "=f"(hi) : "l"(v));
}
__device__ __forceinline__ u64 dup2(float f){ return pk2(f, f); }

// leaky_relu(x) = 0.505*x + 0.495*|x| (slope 0.01), fully packed
__device__ __forceinline__ u64 act_lrelu(u64 v){
    u64 av = v & 0x7FFFFFFF7FFFFFFFULL;
    return fma2(av, 0x3EFD70A43EFD70A4ULL /*0.495*/, mul2(v, 0x3F0147AE3F0147AEULL /*0.505*/));
}
__device__ __forceinline__ float tanh_ap(float x){
    float r; asm("tanh.approx.f32 %0, %1;" : "=f"(r) : "f"(x)); return r;
}
// hidden-layer sigmoid: 0.5*tanh(x/2)+0.5
__device__ __forceinline__ u64 act_sigt(u64 v){
    const u64 half2 = 0x3F0000003F000000ULL;
    u64 v2 = mul2(v, half2);
    float lo, hi; upk2(v2, lo, hi);
    return fma2(pk2(tanh_ap(lo), tanh_ap(hi)), half2, half2);
}
// final-layer sigmoid: near-exact ex2+rcp
__device__ __forceinline__ float fast_sigmoid(float x){
    float e; asm("ex2.approx.f32 %0, %1;" : "=f"(e) : "f"(-1.44269504088896341f * x));
    float r; asm("rcp.approx.f32 %0, %1;" : "=f"(r) : "f"(1.0f + e));
    return r;
}
__device__ __forceinline__ u64 act_sige(u64 v){
    float lo, hi; upk2(v, lo, hi);
    return pk2(fast_sigmoid(lo), fast_sigmoid(hi));
}
// ACT codes: 0 = lrelu, 1 = tanh-sigmoid (hidden), 2 = exact sigmoid (final)
template<int ACT> __device__ __forceinline__ u64 act(u64 v){
    if (ACT == 0) return act_lrelu(v);
    else if (ACT == 1) return act_sigt(v);
    else return act_sige(v);
}

// ---------- X-macro lists ----------
#define J10(F)  F(0) F(1) F(2) F(3) F(4) F(5) F(6) F(7) F(8) F(9)
#define J20(F)  F(0) F(1) F(2) F(3) F(4) F(5) F(6) F(7) F(8) F(9) \
                F(10) F(11) F(12) F(13) F(14) F(15) F(16) F(17) F(18) F(19)
#define JP10(F) F(0,0,1) F(1,2,3) F(2,4,5) F(3,6,7) F(4,8,9) \
                F(5,10,11) F(6,12,13) F(7,14,15) F(8,16,17) F(9,18,19)

// ---------- one full 3-layer path, THREE items, packed-input accumulation ----------
// W1B: 25 pairs x 2 ulonglong2: [(biasPair | w0Pair), (w1Pair | pad)]
// W2W: 250 ulonglong2; quad (p,q): .x = (W2[2p][2q],W2[2p+1][2q]), .y = same for 2q+1
// W3P: 10 ulonglong2; [i].x = (W3[2i][0],W3[2i+1][0]), .y = (W3[2i][1],W3[2i+1][1])
// W2b: 20 u64, (b_j, 0);  W3b: 2 u64, (b_k, 0)
template<int ACT, int ACTF>
__device__ __forceinline__ void path3(const ulonglong2* __restrict__ W1B,
                                      const ulonglong2* __restrict__ W2W,
                                      const ulonglong2* __restrict__ W3P,
                                      const u64* __restrict__ W2b,
                                      const u64* __restrict__ W3b,
                                      u64& hA, u64& hB, u64& hC)
{
    float xa0, xa1, xb0, xb1, xc0, xc1;
    upk2(hA, xa0, xa1); upk2(hB, xb0, xb1); upk2(hC, xc0, xc1);
    u64 D0A = dup2(xa0), D1A = dup2(xa1);
    u64 D0B = dup2(xb0), D1B = dup2(xb1);
    u64 D0C = dup2(xc0), D1C = dup2(xc1);

    // 60 accumulators, lane-split over input index; reduced at the end
    #define DECLJ(j) u64 KA##j = W2b[j]; u64 KB##j = KA##j; u64 KC##j = KA##j;
    J20(DECLJ)
    #undef DECLJ

    const ulonglong2* p1 = W1B;
    const ulonglong2* p2 = W2W;

    #pragma unroll 1
    for (int p = 0; p < 25; p++){
        // layer-1 output pair (a_{2p}, a_{2p+1}) per item; stays packed
        ulonglong2 bw = p1[0];
        u64 w1 = ((const u64*)p1)[2];
        p1 += 2;
        u64 axA = act<ACT>(fma2(D1A, w1, fma2(D0A, bw.y, bw.x)));
        u64 axB = act<ACT>(fma2(D1B, w1, fma2(D0B, bw.y, bw.x)));
        u64 axC = act<ACT>(fma2(D1C, w1, fma2(D0C, bw.y, bw.x)));

        const ulonglong2* rr = p2;
        p2 += 10;
        #define L2Q(q,j0,j1) { ulonglong2 w = rr[q]; \
            KA##j0 = fma2(axA, w.x, KA##j0);  KA##j1 = fma2(axA, w.y, KA##j1); \
            KB##j0 = fma2(axB, w.x, KB##j0);  KB##j1 = fma2(axB, w.y, KB##j1); \
            KC##j0 = fma2(axC, w.x, KC##j0);  KC##j1 = fma2(axC, w.y, KC##j1); }
        JP10(L2Q)
        #undef L2Q
    }

    // reduce lanes, repack as pairs (c_{2i}, c_{2i+1}), activate
    #define RED(i,j0,j1) \
        u64 cA##i, cB##i, cC##i; { float l0,h0,l1,h1; \
        upk2(KA##j0,l0,h0); upk2(KA##j1,l1,h1); cA##i = act<ACT>(pk2(l0+h0, l1+h1)); \
        upk2(KB##j0,l0,h0); upk2(KB##j1,l1,h1); cB##i = act<ACT>(pk2(l0+h0, l1+h1)); \
        upk2(KC##j0,l0,h0); upk2(KC##j1,l1,h1); cC##i = act<ACT>(pk2(l0+h0, l1+h1)); }
    JP10(RED)
    #undef RED

    // layer 3, packed-input: r_k lane-split, reduced at end
    u64 r0A = W3b[0], r1A = W3b[1];
    u64 r0B = r0A, r1B = r1A;
    u64 r0C = r0A, r1C = r1A;
    #define L3Q(i) { ulonglong2 w = W3P[i]; \
        r0A = fma2(cA##i, w.x, r0A);  r1A = fma2(cA##i, w.y, r1A); \
        r0B = fma2(cB##i, w.x, r0B);  r1B = fma2(cB##i, w.y, r1B); \
        r0C = fma2(cC##i, w.x, r0C);  r1C = fma2(cC##i, w.y, r1C); }
    J10(L3Q)
    #undef L3Q

    { float a,b,c,d; upk2(r0A,a,b); upk2(r1A,c,d); hA = act<ACTF>(pk2(a+b, c+d)); }
    { float a,b,c,d; upk2(r0B,a,b); upk2(r1B,c,d); hB = act<ACTF>(pk2(a+b, c+d)); }
    { float a,b,c,d; upk2(r0C,a,b); upk2(r1C,c,d); hC = act<ACTF>(pk2(a+b, c+d)); }
}

// ---------- shared fills (element-wise scalar, no per-thread arrays) ----------
// L1: 25 pairs x 8 floats: {b[2p],b[2p+1], W1[0][2p],W1[0][2p+1], W1[1][2p],W1[1][2p+1], 0,0}
__device__ void fill_L1(float* dstf, const float* __restrict__ W,
                        const float* __restrict__ Bv)
{
    for (int e = threadIdx.x; e < 200; e += blockDim.x){
        int p = e >> 3, k = e & 7;
        float v = 0.0f;
        if      (k < 2) v = Bv[2*p + k];
        else if (k < 4) v = W[      2*p + (k-2)];
        else if (k < 6) v = W[50 +  2*p + (k-4)];
        dstf[e] = v;
    }
}
// W2 pairs: u64 (p,j) = (W2[2p][j], W2[2p+1][j]); 1000 floats
__device__ void fill_W2(float* dstf, const float* __restrict__ W)
{
    for (int e = threadIdx.x; e < 1000; e += blockDim.x){
        int g = e >> 1, lane = e & 1;
        int p = g / 20, j = g % 20;
        dstf[e] = W[(2*p + lane)*20 + j];
    }
}
// W3 pairs: ulonglong2 [i]: 4 floats {W3[2i][0],W3[2i+1][0],W3[2i][1],W3[2i+1][1]}
__device__ void fill_W3P(float* dstf, const float* __restrict__ W)
{
    for (int e = threadIdx.x; e < 40; e += blockDim.x){
        int i = e >> 2, t = e & 3;
        dstf[e] = W[(2*i + (t & 1))*2 + (t >> 1)];
    }
}
// bias as (b, 0) u64s: 2n floats
__device__ void fill_bias2(float* dstf, const float* __restrict__ b, int n)
{
    for (int e = threadIdx.x; e < 2*n; e += blockDim.x){
        dstf[e] = (e & 1) ? 0.0f : b[e >> 1];
    }
}

// sQ layout (ulonglong2): H: L1@0(50) W2@50(250) W3P@300(10); Z: @310 same
// sP layout (u64): H: w2b@0(20) w3b@20(2); Z: @22
__global__ void __launch_bounds__(128)
recurrent_kernel(const float2* __restrict__ win,
                 const float* __restrict__ Wh1, const float* __restrict__ bh1,
                 const float* __restrict__ Wh2, const float* __restrict__ bh2,
                 const float* __restrict__ Wh3, const float* __restrict__ bh3,
                 const float* __restrict__ Wz1, const float* __restrict__ bz1,
                 const float* __restrict__ Wz2, const float* __restrict__ bz2,
                 const float* __restrict__ Wz3, const float* __restrict__ bz3,
                 float2* __restrict__ out, int Q, int B)
{
    __shared__ ulonglong2 sQ[620];
    __shared__ u64 sP[44];

    fill_L1   ((float*)(sQ +   0), Wh1, bh1);
    fill_W2   ((float*)(sQ +  50), Wh2);
    fill_W3P  ((float*)(sQ + 300), Wh3);
    fill_L1   ((float*)(sQ + 310), Wz1, bz1);
    fill_W2   ((float*)(sQ + 360), Wz2);
    fill_W3P  ((float*)(sQ + 610), Wz3);
    fill_bias2((float*)(sP +   0), bh2, 20);
    fill_bias2((float*)(sP +  20), bh3,  2);
    fill_bias2((float*)(sP +  22), bz2, 20);
    fill_bias2((float*)(sP +  42), bz3,  2);
    __syncthreads();

    int tid = blockIdx.x * blockDim.x + threadIdx.x;
    if (tid >= Q) return;

    int idxA = tid;
    int idxB = tid + Q;
    int idxC = tid + 2 * Q;
    bool hasC = (idxC < B);
    int idxCl = hasC ? idxC : (B - 1);

    float2 hinA = win[idxA];
    float2 hinB = win[idxB];
    float2 hinC = win[idxCl];
    u64 hA = pk2(hinA.x, hinA.y);
    u64 hB = pk2(hinB.x, hinB.y);
    u64 hC = pk2(hinC.x, hinC.y);

    float2* opA = out + (size_t)idxA * 19;
    float2* opB = out + (size_t)idxB * 19;
    float2* opC = out + (size_t)idxCl * 19;

    #pragma unroll 1
    for (int t = 0; t < 19; t++){
        // h path: leaky relu everywhere
        path3<0, 0>(sQ +   0, sQ +  50, sQ + 300, sP +  0, sP + 20, hA, hB, hC);
        // z path: tanh-sigmoid hidden, exact sigmoid final
        u64 zA = hA, zB = hB, zC = hC;
        path3<1, 2>(sQ + 310, sQ + 360, sQ + 610, sP + 22, sP + 42, zA, zB, zC);
        float lo, hi;
        upk2(zA, lo, hi); opA[t] = make_float2(lo, hi);
        upk2(zB, lo, hi); opB[t] = make_float2(lo, hi);
        if (hasC) { upk2(zC, lo, hi); opC[t] = make_float2(lo, hi); }
    }
}

extern "C" void kernel_launch(void* const* d_in, const int* in_sizes, int n_in,
                              void* d_out, int out_size)
{
    const float* w   = (const float*)d_in[0];
    const float* Wh1 = (const float*)d_in[1];
    const float* bh1 = (const float*)d_in[2];
    const float* Wh2 = (const float*)d_in[3];
    const float* bh2 = (const float*)d_in[4];
    const float* Wh3 = (const float*)d_in[5];
    const float* bh3 = (const float*)d_in[6];
    const float* Wz1 = (const float*)d_in[7];
    const float* bz1 = (const float*)d_in[8];
    const float* Wz2 = (const float*)d_in[9];
    const float* bz2 = (const float*)d_in[10];
    const float* Wz3 = (const float*)d_in[11];
    const float* bz3 = (const float*)d_in[12];

    int B = in_sizes[0] / 2;            // 1048576
    int Q = (B + 2) / 3;
    int threads = 128;
    int blocks = (Q + threads - 1) / threads;
    recurrent_kernel<<<blocks, threads>>>((const float2*)w,
                                          Wh1, bh1, Wh2, bh2, Wh3, bh3,
                                          Wz1, bz1, Wz2, bz2, Wz3, bz3,
                                          (float2*)d_out, Q, B);
}

// round 12
// speedup vs baseline: 1.3524x; 1.3524x over previous
#include <cuda_runtime.h>

typedef unsigned long long u64;

// ---------- packed f32x2 helpers ----------
__device__ __forceinline__ u64 fma2(u64 a, u64 b, u64 c){
    u64 d; asm("fma.rn.f32x2 %0, %1, %2, %3;" : "=l"(d) : "l"(a), "l"(b), "l"(c)); return d;
}
__device__ __forceinline__ u64 mul2(u64 a, u64 b){
    u64 d; asm("mul.rn.f32x2 %0, %1, %2;" : "=l"(d) : "l"(a), "l"(b)); return d;
}
__device__ __forceinline__ u64 pk2(float lo, float hi){
    u64 d; asm("mov.b64 %0, {%1, %2};" : "=l"(d) : "f"(lo), "f"(hi)); return d;
}
__device__ __forceinline__ void upk2(u64 v, float& lo, float& hi){
    asm("mov.b64 {%0, %1}, %2;" : "=f"(lo), "=f"(hi) : "l"(v));
}
__device__ __forceinline__ u64 dup2(float f){ return pk2(f, f); }

// leaky_relu(x) = 0.505*x + 0.495*|x| (slope 0.01), fully packed
__device__ __forceinline__ u64 act_lrelu(u64 v){
    u64 av = v & 0x7FFFFFFF7FFFFFFFULL;
    return fma2(av, 0x3EFD70A43EFD70A4ULL /*0.495*/, mul2(v, 0x3F0147AE3F0147AEULL /*0.505*/));
}
__device__ __forceinline__ float tanh_ap(float x){
    float r; asm("tanh.approx.f32 %0, %1;" : "=f"(r) : "f"(x)); return r;
}
// hidden-layer sigmoid: 0.5*tanh(x/2)+0.5
__device__ __forceinline__ u64 act_sigt(u64 v){
    const u64 half2 = 0x3F0000003F000000ULL;
    u64 v2 = mul2(v, half2);
    float lo, hi; upk2(v2, lo, hi);
    return fma2(pk2(tanh_ap(lo), tanh_ap(hi)), half2, half2);
}
// final-layer sigmoid: near-exact ex2+rcp
__device__ __forceinline__ float fast_sigmoid(float x){
    float e; asm("ex2.approx.f32 %0, %1;" : "=f"(e) : "f"(-1.44269504088896341f * x));
    float r; asm("rcp.approx.f32 %0, %1;" : "=f"(r) : "f"(1.0f + e));
    return r;
}
__device__ __forceinline__ u64 act_sige(u64 v){
    float lo, hi; upk2(v, lo, hi);
    return pk2(fast_sigmoid(lo), fast_sigmoid(hi));
}
// ACT codes: 0 = lrelu, 1 = tanh-sigmoid (hidden), 2 = exact sigmoid (final)
template<int ACT> __device__ __forceinline__ u64 act(u64 v){
    if (ACT == 0) return act_lrelu(v);
    else if (ACT == 1) return act_sigt(v);
    else return act_sige(v);
}

// scatter one loaded quad into all three items' accumulator pairs
#define SCAT(qv, a0, a1) \
    CA##a0 = fma2(ddA, (qv).x, CA##a0);  CB##a0 = fma2(ddB, (qv).x, CB##a0);  CC##a0 = fma2(ddC, (qv).x, CC##a0); \
    CA##a1 = fma2(ddA, (qv).y, CA##a1);  CB##a1 = fma2(ddB, (qv).y, CB##a1);  CC##a1 = fma2(ddC, (qv).y, CC##a1);

// layer-3 step for one accumulator pair (rows 2i, 2i+1), three items
#define L3STEP(Ci, wlo_idx) { \
    float loA, hiA, loB, hiB, loC, hiC; \
    upk2(CA##Ci, loA, hiA); upk2(CB##Ci, loB, hiB); upk2(CC##Ci, loC, hiC); \
    u64 wl = W3B[wlo_idx], wh = W3B[(wlo_idx)+1]; \
    resA = fma2(dup2(loA), wl, resA);  resB = fma2(dup2(loB), wl, resB);  resC = fma2(dup2(loC), wl, resC); \
    resA = fma2(dup2(hiA), wh, resA);  resB = fma2(dup2(hiB), wh, resB);  resC = fma2(dup2(hiC), wh, resC); }

// one inner iteration body (layer-1 pair p -> scatter into layer-2 accumulators)
#define ITER_BODY { \
    ulonglong2 bw = p1[0]; \
    u64 w1 = ((const u64*)p1)[2]; \
    p1 += 2; \
    u64 axA = fma2(D0A, bw.y, bw.x); axA = fma2(D1A, w1, axA); axA = act<ACT>(axA); \
    u64 axB = fma2(D0B, bw.y, bw.x); axB = fma2(D1B, w1, axB); axB = act<ACT>(axB); \
    u64 axC = fma2(D0C, bw.y, bw.x); axC = fma2(D1C, w1, axC); axC = act<ACT>(axC); \
    float f0A, f1A, f0B, f1B, f0C, f1C; \
    upk2(axA, f0A, f1A); upk2(axB, f0B, f1B); upk2(axC, f0C, f1C); \
    { \
        u64 ddA = dup2(f0A), ddB = dup2(f0B), ddC = dup2(f0C); \
        ulonglong2 q; \
        q = p2[0]; SCAT(q, 0, 1) \
        q = p2[1]; SCAT(q, 2, 3) \
        q = p2[2]; SCAT(q, 4, 5) \
        q = p2[3]; SCAT(q, 6, 7) \
        q = p2[4]; SCAT(q, 8, 9) \
    } \
    { \
        u64 ddA = dup2(f1A), ddB = dup2(f1B), ddC = dup2(f1C); \
        ulonglong2 q; \
        q = p2[5]; SCAT(q, 0, 1) \
        q = p2[6]; SCAT(q, 2, 3) \
        q = p2[7]; SCAT(q, 4, 5) \
        q = p2[8]; SCAT(q, 6, 7) \
        q = p2[9]; SCAT(q, 8, 9) \
    } \
    p2 += 10; }

// ---------- one full 3-layer path, THREE batch items at once ----------
// W1B: 25 pairs x 2 ulonglong2: [ (bias_pair | w_row0_pair), (w_row1_pair | pad) ]
// W2B: [bias: 5 quads][row r: 5 quads each], r = 0..49
// W3B: [bias pair][row r pair], r = 0..19   (u64 units)
template<int ACT, int ACTF>
__device__ __forceinline__ void path3(const ulonglong2* __restrict__ W1B,
                                      const ulonglong2* __restrict__ W2B,
                                      const u64* __restrict__ W3B,
                                      u64& hA, u64& hB, u64& hC)
{
    float xa0, xa1, xb0, xb1, xc0, xc1;
    upk2(hA, xa0, xa1); upk2(hB, xb0, xb1); upk2(hC, xc0, xc1);
    u64 D0A = dup2(xa0), D1A = dup2(xa1);
    u64 D0B = dup2(xb0), D1B = dup2(xb1);
    u64 D0C = dup2(xc0), D1C = dup2(xc1);

    u64 CA0, CA1, CA2, CA3, CA4, CA5, CA6, CA7, CA8, CA9;
    u64 CB0, CB1, CB2, CB3, CB4, CB5, CB6, CB7, CB8, CB9;
    u64 CC0, CC1, CC2, CC3, CC4, CC5, CC6, CC7, CC8, CC9;
    { ulonglong2 b = W2B[0]; CA0 = b.x; CA1 = b.y; CB0 = b.x; CB1 = b.y; CC0 = b.x; CC1 = b.y; }
    { ulonglong2 b = W2B[1]; CA2 = b.x; CA3 = b.y; CB2 = b.x; CB3 = b.y; CC2 = b.x; CC3 = b.y; }
    { ulonglong2 b = W2B[2]; CA4 = b.x; CA5 = b.y; CB4 = b.x; CB5 = b.y; CC4 = b.x; CC5 = b.y; }
    { ulonglong2 b = W2B[3]; CA6 = b.x; CA7 = b.y; CB6 = b.x; CB7 = b.y; CC6 = b.x; CC7 = b.y; }
    { ulonglong2 b = W2B[4]; CA8 = b.x; CA9 = b.y; CB8 = b.x; CB9 = b.y; CC8 = b.x; CC9 = b.y; }

    const ulonglong2* p1 = W1B;
    const ulonglong2* p2 = W2B + 5;

    // 24 iterations with a 2-wide scheduling window (software pipelining),
    // then the 25th explicitly.
    #pragma unroll 2
    for (int p = 0; p < 24; p++){
        ITER_BODY
    }
    ITER_BODY

    CA0 = act<ACT>(CA0); CA1 = act<ACT>(CA1); CA2 = act<ACT>(CA2); CA3 = act<ACT>(CA3);
    CA4 = act<ACT>(CA4); CA5 = act<ACT>(CA5); CA6 = act<ACT>(CA6); CA7 = act<ACT>(CA7);
    CA8 = act<ACT>(CA8); CA9 = act<ACT>(CA9);
    CB0 = act<ACT>(CB0); CB1 = act<ACT>(CB1); CB2 = act<ACT>(CB2); CB3 = act<ACT>(CB3);
    CB4 = act<ACT>(CB4); CB5 = act<ACT>(CB5); CB6 = act<ACT>(CB6); CB7 = act<ACT>(CB7);
    CB8 = act<ACT>(CB8); CB9 = act<ACT>(CB9);
    CC0 = act<ACT>(CC0); CC1 = act<ACT>(CC1); CC2 = act<ACT>(CC2); CC3 = act<ACT>(CC3);
    CC4 = act<ACT>(CC4); CC5 = act<ACT>(CC5); CC6 = act<ACT>(CC6); CC7 = act<ACT>(CC7);
    CC8 = act<ACT>(CC8); CC9 = act<ACT>(CC9);

    // layer 3: 20 inputs -> 1 packed output pair, all items
    u64 resA = W3B[0];
    u64 resB = resA;
    u64 resC = resA;
    L3STEP(0,  1)
    L3STEP(1,  3)
    L3STEP(2,  5)
    L3STEP(3,  7)
    L3STEP(4,  9)
    L3STEP(5, 11)
    L3STEP(6, 13)
    L3STEP(7, 15)
    L3STEP(8, 17)
    L3STEP(9, 19)

    hA = act<ACTF>(resA);
    hB = act<ACTF>(resB);
    hC = act<ACTF>(resC);
}

// ---------- shared fills (element-wise scalar, no per-thread arrays) ----------
// L1 block: 25 pairs x 8 floats: {b[2p],b[2p+1], W[0][2p],W[0][2p+1], W[1][2p],W[1][2p+1], 0,0}
__device__ void fill_L1(float* dstf, const float* __restrict__ W,
                        const float* __restrict__ Bv)
{
    for (int e = threadIdx.x; e < 200; e += blockDim.x){
        int p = e >> 3, k = e & 7;
        float v = 0.0f;
        if      (k < 2) v = Bv[2*p + k];
        else if (k < 4) v = W[      2*p + (k-2)];   // row 0 of W[2][50]
        else if (k < 6) v = W[50 +  2*p + (k-4)];   // row 1
        dstf[e] = v;
    }
}
// L2 block (float view): [bias: 20][row r: 20 floats], r=0..49
__device__ void fill_L2(float* dstf, const float* __restrict__ W,
                        const float* __restrict__ Bv)
{
    for (int e = threadIdx.x; e < 1020; e += blockDim.x){
        int blk = e / 20, j = e % 20;
        dstf[e] = (blk == 0) ? Bv[j] : W[(blk - 1) * 20 + j];
    }
}
// L3 block (float view): [b0,b1][row r: W[2r], W[2r+1]], r=0..19
__device__ void fill_L3(float* dstf, const float* __restrict__ W,
                        const float* __restrict__ Bv)
{
    for (int e = threadIdx.x; e < 42; e += blockDim.x){
        int blk = e >> 1, j = e & 1;
        dstf[e] = (blk == 0) ? Bv[j] : W[(blk - 1) * 2 + j];
    }
}

// shared layout (ulonglong2 units): H1@0(50)  H2@50(255)  Z1@305(50)  Z2@355(255)
__global__ void __launch_bounds__(128)
recurrent_kernel(const float2* __restrict__ win,
                 const float* __restrict__ Wh1, const float* __restrict__ bh1,
                 const float* __restrict__ Wh2, const float* __restrict__ bh2,
                 const float* __restrict__ Wh3, const float* __restrict__ bh3,
                 const float* __restrict__ Wz1, const float* __restrict__ bz1,
                 const float* __restrict__ Wz2, const float* __restrict__ bz2,
                 const float* __restrict__ Wz3, const float* __restrict__ bz3,
                 float2* __restrict__ out, int Q, int B)
{
    __shared__ ulonglong2 sQ[610];
    __shared__ u64 sP[44];     // H3 @0 (21), Z3 @22 (21)

    fill_L1((float*)(sQ +   0), Wh1, bh1);
    fill_L2((float*)(sQ +  50), Wh2, bh2);
    fill_L1((float*)(sQ + 305), Wz1, bz1);
    fill_L2((float*)(sQ + 355), Wz2, bz2);
    fill_L3((float*)(sP +   0), Wh3, bh3);
    fill_L3((float*)(sP +  22), Wz3, bz3);
    __syncthreads();

    int tid = blockIdx.x * blockDim.x + threadIdx.x;
    if (tid >= Q) return;

    int idxA = tid;
    int idxB = tid + Q;
    int idxC = tid + 2 * Q;
    bool hasC = (idxC < B);
    int idxCl = hasC ? idxC : (B - 1);

    float2 hinA = win[idxA];
    float2 hinB = win[idxB];
    float2 hinC = win[idxCl];
    u64 hA = pk2(hinA.x, hinA.y);
    u64 hB = pk2(hinB.x, hinB.y);
    u64 hC = pk2(hinC.x, hinC.y);

    float2* opA = out + (size_t)idxA * 19;
    float2* opB = out + (size_t)idxB * 19;
    float2* opC = out + (size_t)idxCl * 19;

    #pragma unroll 1
    for (int t = 0; t < 19; t++){
        path3<0, 0>(sQ +   0, sQ +  50, sP +  0, hA, hB, hC);   // h path: leaky relu
        u64 zA = hA, zB = hB, zC = hC;
        path3<1, 2>(sQ + 305, sQ + 355, sP + 22, zA, zB, zC);   // z: tanh hidden, exact final
        float lo, hi;
        upk2(zA, lo, hi); opA[t] = make_float2(lo, hi);
        upk2(zB, lo, hi); opB[t] = make_float2(lo, hi);
        if (hasC) { upk2(zC, lo, hi); opC[t] = make_float2(lo, hi); }
    }
}

extern "C" void kernel_launch(void* const* d_in, const int* in_sizes, int n_in,
                              void* d_out, int out_size)
{
    const float* w   = (const float*)d_in[0];
    const float* Wh1 = (const float*)d_in[1];
    const float* bh1 = (const float*)d_in[2];
    const float* Wh2 = (const float*)d_in[3];
    const float* bh2 = (const float*)d_in[4];
    const float* Wh3 = (const float*)d_in[5];
    const float* bh3 = (const float*)d_in[6];
    const float* Wz1 = (const float*)d_in[7];
    const float* bz1 = (const float*)d_in[8];
    const float* Wz2 = (const float*)d_in[9];
    const float* bz2 = (const float*)d_in[10];
    const float* Wz3 = (const float*)d_in[11];
    const float* bz3 = (const float*)d_in[12];

    int B = in_sizes[0] / 2;            // 1048576
    int Q = (B + 2) / 3;
    int threads = 128;
    int blocks = (Q + threads - 1) / threads;
    recurrent_kernel<<<blocks, threads>>>((const float2*)w,
                                          Wh1, bh1, Wh2, bh2, Wh3, bh3,
                                          Wz1, bz1, Wz2, bz2, Wz3, bz3,
                                          (float2*)d_out, Q, B);
}

// round 13
// speedup vs baseline: 1.3857x; 1.0247x over previous
#include <cuda_runtime.h>

typedef unsigned long long u64;

// ---------- packed f32x2 helpers ----------
__device__ __forceinline__ u64 fma2(u64 a, u64 b, u64 c){
    u64 d; asm("fma.rn.f32x2 %0, %1, %2, %3;" : "=l"(d) : "l"(a), "l"(b), "l"(c)); return d;
}
__device__ __forceinline__ u64 mul2(u64 a, u64 b){
    u64 d; asm("mul.rn.f32x2 %0, %1, %2;" : "=l"(d) : "l"(a), "l"(b)); return d;
}
__device__ __forceinline__ u64 pk2(float lo, float hi){
    u64 d; asm("mov.b64 %0, {%1, %2};" : "=l"(d) : "f"(lo), "f"(hi)); return d;
}
__device__ __forceinline__ void upk2(u64 v, float& lo, float& hi){
    asm("mov.b64 {%0, %1}, %2;" : "=f"(lo), "=f"(hi) : "l"(v));
}
__device__ __forceinline__ u64 dup2(float f){ return pk2(f, f); }

// leaky_relu(x) = 0.505*x + 0.495*|x| (slope 0.01), fully packed
__device__ __forceinline__ u64 act_lrelu(u64 v){
    u64 av = v & 0x7FFFFFFF7FFFFFFFULL;
    return fma2(av, 0x3EFD70A43EFD70A4ULL /*0.495*/, mul2(v, 0x3F0147AE3F0147AEULL /*0.505*/));
}
__device__ __forceinline__ float tanh_ap(float x){
    float r; asm("tanh.approx.f32 %0, %1;" : "=f"(r) : "f"(x)); return r;
}
// hidden-layer sigmoid: 0.5*tanh(x/2)+0.5
__device__ __forceinline__ u64 act_sigt(u64 v){
    const u64 half2 = 0x3F0000003F000000ULL;
    u64 v2 = mul2(v, half2);
    float lo, hi; upk2(v2, lo, hi);
    return fma2(pk2(tanh_ap(lo), tanh_ap(hi)), half2, half2);
}
// final-layer sigmoid: near-exact ex2+rcp
__device__ __forceinline__ float fast_sigmoid(float x){
    float e; asm("ex2.approx.f32 %0, %1;" : "=f"(e) : "f"(-1.44269504088896341f * x));
    float r; asm("rcp.approx.f32 %0, %1;" : "=f"(r) : "f"(1.0f + e));
    return r;
}
__device__ __forceinline__ u64 act_sige(u64 v){
    float lo, hi; upk2(v, lo, hi);
    return pk2(fast_sigmoid(lo), fast_sigmoid(hi));
}
// ACT codes: 0 = lrelu, 1 = tanh-sigmoid (hidden), 2 = exact sigmoid (final)
template<int ACT> __device__ __forceinline__ u64 act(u64 v){
    if (ACT == 0) return act_lrelu(v);
    else if (ACT == 1) return act_sigt(v);
    else return act_sige(v);
}

// scatter one loaded quad into all three items' accumulator pairs
#define SCAT(qv, a0, a1) \
    CA##a0 = fma2(ddA, (qv).x, CA##a0);  CB##a0 = fma2(ddB, (qv).x, CB##a0);  CC##a0 = fma2(ddC, (qv).x, CC##a0); \
    CA##a1 = fma2(ddA, (qv).y, CA##a1);  CB##a1 = fma2(ddB, (qv).y, CB##a1);  CC##a1 = fma2(ddC, (qv).y, CC##a1);

// layer-3 step for one accumulator pair (rows 2i, 2i+1), three items
#define L3STEP(Ci, wlo_idx) { \
    float loA, hiA, loB, hiB, loC, hiC; \
    upk2(CA##Ci, loA, hiA); upk2(CB##Ci, loB, hiB); upk2(CC##Ci, loC, hiC); \
    u64 wl = W3B[wlo_idx], wh = W3B[(wlo_idx)+1]; \
    resA = fma2(dup2(loA), wl, resA);  resB = fma2(dup2(loB), wl, resB);  resC = fma2(dup2(loC), wl, resC); \
    resA = fma2(dup2(hiA), wh, resA);  resB = fma2(dup2(hiB), wh, resB);  resC = fma2(dup2(hiC), wh, resC); }

// one inner iteration body (layer-1 pair p -> scatter into layer-2 accumulators)
#define ITER_BODY { \
    ulonglong2 bw = p1[0]; \
    u64 w1 = ((const u64*)p1)[2]; \
    p1 += 2; \
    u64 axA = fma2(D0A, bw.y, bw.x); axA = fma2(D1A, w1, axA); axA = act<ACT>(axA); \
    u64 axB = fma2(D0B, bw.y, bw.x); axB = fma2(D1B, w1, axB); axB = act<ACT>(axB); \
    u64 axC = fma2(D0C, bw.y, bw.x); axC = fma2(D1C, w1, axC); axC = act<ACT>(axC); \
    float f0A, f1A, f0B, f1B, f0C, f1C; \
    upk2(axA, f0A, f1A); upk2(axB, f0B, f1B); upk2(axC, f0C, f1C); \
    { \
        u64 ddA = dup2(f0A), ddB = dup2(f0B), ddC = dup2(f0C); \
        ulonglong2 q; \
        q = p2[0]; SCAT(q, 0, 1) \
        q = p2[1]; SCAT(q, 2, 3) \
        q = p2[2]; SCAT(q, 4, 5) \
        q = p2[3]; SCAT(q, 6, 7) \
        q = p2[4]; SCAT(q, 8, 9) \
    } \
    { \
        u64 ddA = dup2(f1A), ddB = dup2(f1B), ddC = dup2(f1C); \
        ulonglong2 q; \
        q = p2[5]; SCAT(q, 0, 1) \
        q = p2[6]; SCAT(q, 2, 3) \
        q = p2[7]; SCAT(q, 4, 5) \
        q = p2[8]; SCAT(q, 6, 7) \
        q = p2[9]; SCAT(q, 8, 9) \
    } \
    p2 += 10; }

// ---------- one full 3-layer path, THREE batch items at once ----------
// W1B: 25 pairs x 2 ulonglong2: [ (bias_pair | w_row0_pair), (w_row1_pair | pad) ]
// W2B: [bias: 5 quads][row r: 5 quads each], r = 0..49
// W3B: [bias pair][row r pair], r = 0..19   (u64 units)
template<int ACT, int ACTF>
__device__ __forceinline__ void path3(const ulonglong2* __restrict__ W1B,
                                      const ulonglong2* __restrict__ W2B,
                                      const u64* __restrict__ W3B,
                                      u64& hA, u64& hB, u64& hC)
{
    float xa0, xa1, xb0, xb1, xc0, xc1;
    upk2(hA, xa0, xa1); upk2(hB, xb0, xb1); upk2(hC, xc0, xc1);
    u64 D0A = dup2(xa0), D1A = dup2(xa1);
    u64 D0B = dup2(xb0), D1B = dup2(xb1);
    u64 D0C = dup2(xc0), D1C = dup2(xc1);

    u64 CA0, CA1, CA2, CA3, CA4, CA5, CA6, CA7, CA8, CA9;
    u64 CB0, CB1, CB2, CB3, CB4, CB5, CB6, CB7, CB8, CB9;
    u64 CC0, CC1, CC2, CC3, CC4, CC5, CC6, CC7, CC8, CC9;
    { ulonglong2 b = W2B[0]; CA0 = b.x; CA1 = b.y; CB0 = b.x; CB1 = b.y; CC0 = b.x; CC1 = b.y; }
    { ulonglong2 b = W2B[1]; CA2 = b.x; CA3 = b.y; CB2 = b.x; CB3 = b.y; CC2 = b.x; CC3 = b.y; }
    { ulonglong2 b = W2B[2]; CA4 = b.x; CA5 = b.y; CB4 = b.x; CB5 = b.y; CC4 = b.x; CC5 = b.y; }
    { ulonglong2 b = W2B[3]; CA6 = b.x; CA7 = b.y; CB6 = b.x; CB7 = b.y; CC6 = b.x; CC7 = b.y; }
    { ulonglong2 b = W2B[4]; CA8 = b.x; CA9 = b.y; CB8 = b.x; CB9 = b.y; CC8 = b.x; CC9 = b.y; }

    const ulonglong2* p1 = W1B;
    const ulonglong2* p2 = W2B + 5;

    // 24 iterations with a 4-wide scheduling window (software pipelining),
    // then the 25th explicitly.
    #pragma unroll 4
    for (int p = 0; p < 24; p++){
        ITER_BODY
    }
    ITER_BODY

    CA0 = act<ACT>(CA0); CA1 = act<ACT>(CA1); CA2 = act<ACT>(CA2); CA3 = act<ACT>(CA3);
    CA4 = act<ACT>(CA4); CA5 = act<ACT>(CA5); CA6 = act<ACT>(CA6); CA7 = act<ACT>(CA7);
    CA8 = act<ACT>(CA8); CA9 = act<ACT>(CA9);
    CB0 = act<ACT>(CB0); CB1 = act<ACT>(CB1); CB2 = act<ACT>(CB2); CB3 = act<ACT>(CB3);
    CB4 = act<ACT>(CB4); CB5 = act<ACT>(CB5); CB6 = act<ACT>(CB6); CB7 = act<ACT>(CB7);
    CB8 = act<ACT>(CB8); CB9 = act<ACT>(CB9);
    CC0 = act<ACT>(CC0); CC1 = act<ACT>(CC1); CC2 = act<ACT>(CC2); CC3 = act<ACT>(CC3);
    CC4 = act<ACT>(CC4); CC5 = act<ACT>(CC5); CC6 = act<ACT>(CC6); CC7 = act<ACT>(CC7);
    CC8 = act<ACT>(CC8); CC9 = act<ACT>(CC9);

    // layer 3: 20 inputs -> 1 packed output pair, all items
    u64 resA = W3B[0];
    u64 resB = resA;
    u64 resC = resA;
    L3STEP(0,  1)
    L3STEP(1,  3)
    L3STEP(2,  5)
    L3STEP(3,  7)
    L3STEP(4,  9)
    L3STEP(5, 11)
    L3STEP(6, 13)
    L3STEP(7, 15)
    L3STEP(8, 17)
    L3STEP(9, 19)

    hA = act<ACTF>(resA);
    hB = act<ACTF>(resB);
    hC = act<ACTF>(resC);
}

// ---------- shared fills (element-wise scalar, no per-thread arrays) ----------
// L1 block: 25 pairs x 8 floats: {b[2p],b[2p+1], W[0][2p],W[0][2p+1], W[1][2p],W[1][2p+1], 0,0}
__device__ void fill_L1(float* dstf, const float* __restrict__ W,
                        const float* __restrict__ Bv)
{
    for (int e = threadIdx.x; e < 200; e += blockDim.x){
        int p = e >> 3, k = e & 7;
        float v = 0.0f;
        if      (k < 2) v = Bv[2*p + k];
        else if (k < 4) v = W[      2*p + (k-2)];   // row 0 of W[2][50]
        else if (k < 6) v = W[50 +  2*p + (k-4)];   // row 1
        dstf[e] = v;
    }
}
// L2 block (float view): [bias: 20][row r: 20 floats], r=0..49
__device__ void fill_L2(float* dstf, const float* __restrict__ W,
                        const float* __restrict__ Bv)
{
    for (int e = threadIdx.x; e < 1020; e += blockDim.x){
        int blk = e / 20, j = e % 20;
        dstf[e] = (blk == 0) ? Bv[j] : W[(blk - 1) * 20 + j];
    }
}
// L3 block (float view): [b0,b1][row r: W[2r], W[2r+1]], r=0..19
__device__ void fill_L3(float* dstf, const float* __restrict__ W,
                        const float* __restrict__ Bv)
{
    for (int e = threadIdx.x; e < 42; e += blockDim.x){
        int blk = e >> 1, j = e & 1;
        dstf[e] = (blk == 0) ? Bv[j] : W[(blk - 1) * 2 + j];
    }
}

// shared layout (ulonglong2 units): H1@0(50)  H2@50(255)  Z1@305(50)  Z2@355(255)
__global__ void __launch_bounds__(128)
recurrent_kernel(const float2* __restrict__ win,
                 const float* __restrict__ Wh1, const float* __restrict__ bh1,
                 const float* __restrict__ Wh2, const float* __restrict__ bh2,
                 const float* __restrict__ Wh3, const float* __restrict__ bh3,
                 const float* __restrict__ Wz1, const float* __restrict__ bz1,
                 const float* __restrict__ Wz2, const float* __restrict__ bz2,
                 const float* __restrict__ Wz3, const float* __restrict__ bz3,
                 float2* __restrict__ out, int Q, int B)
{
    __shared__ ulonglong2 sQ[610];
    __shared__ u64 sP[44];     // H3 @0 (21), Z3 @22 (21)

    fill_L1((float*)(sQ +   0), Wh1, bh1);
    fill_L2((float*)(sQ +  50), Wh2, bh2);
    fill_L1((float*)(sQ + 305), Wz1, bz1);
    fill_L2((float*)(sQ + 355), Wz2, bz2);
    fill_L3((float*)(sP +   0), Wh3, bh3);
    fill_L3((float*)(sP +  22), Wz3, bz3);
    __syncthreads();

    int tid = blockIdx.x * blockDim.x + threadIdx.x;
    if (tid >= Q) return;

    int idxA = tid;
    int idxB = tid + Q;
    int idxC = tid + 2 * Q;
    bool hasC = (idxC < B);
    int idxCl = hasC ? idxC : (B - 1);

    float2 hinA = win[idxA];
    float2 hinB = win[idxB];
    float2 hinC = win[idxCl];
    u64 hA = pk2(hinA.x, hinA.y);
    u64 hB = pk2(hinB.x, hinB.y);
    u64 hC = pk2(hinC.x, hinC.y);

    float2* opA = out + (size_t)idxA * 19;
    float2* opB = out + (size_t)idxB * 19;
    float2* opC = out + (size_t)idxCl * 19;

    #pragma unroll 1
    for (int t = 0; t < 19; t++){
        path3<0, 0>(sQ +   0, sQ +  50, sP +  0, hA, hB, hC);   // h path: leaky relu
        u64 zA = hA, zB = hB, zC = hC;
        path3<1, 2>(sQ + 305, sQ + 355, sP + 22, zA, zB, zC);   // z: tanh hidden, exact final
        float lo, hi;
        upk2(zA, lo, hi); opA[t] = make_float2(lo, hi);
        upk2(zB, lo, hi); opB[t] = make_float2(lo, hi);
        if (hasC) { upk2(zC, lo, hi); opC[t] = make_float2(lo, hi); }
    }
}

extern "C" void kernel_launch(void* const* d_in, const int* in_sizes, int n_in,
                              void* d_out, int out_size)
{
    const float* w   = (const float*)d_in[0];
    const float* Wh1 = (const float*)d_in[1];
    const float* bh1 = (const float*)d_in[2];
    const float* Wh2 = (const float*)d_in[3];
    const float* bh2 = (const float*)d_in[4];
    const float* Wh3 = (const float*)d_in[5];
    const float* bh3 = (const float*)d_in[6];
    const float* Wz1 = (const float*)d_in[7];
    const float* bz1 = (const float*)d_in[8];
    const float* Wz2 = (const float*)d_in[9];
    const float* bz2 = (const float*)d_in[10];
    const float* Wz3 = (const float*)d_in[11];
    const float* bz3 = (const float*)d_in[12];

    int B = in_sizes[0] / 2;            // 1048576
    int Q = (B + 2) / 3;
    int threads = 128;
    int blocks = (Q + threads - 1) / threads;
    recurrent_kernel<<<blocks, threads>>>((const float2*)w,
                                          Wh1, bh1, Wh2, bh2, Wh3, bh3,
                                          Wz1, bz1, Wz2, bz2, Wz3, bz3,
                                          (float2*)d_out, Q, B);
}

// round 14
// speedup vs baseline: 1.4766x; 1.0656x over previous
#include <cuda_runtime.h>

typedef unsigned long long u64;

// ---------- packed f32x2 helpers ----------
__device__ __forceinline__ u64 fma2(u64 a, u64 b, u64 c){
    u64 d; asm("fma.rn.f32x2 %0, %1, %2, %3;" : "=l"(d) : "l"(a), "l"(b), "l"(c)); return d;
}
__device__ __forceinline__ u64 mul2(u64 a, u64 b){
    u64 d; asm("mul.rn.f32x2 %0, %1, %2;" : "=l"(d) : "l"(a), "l"(b)); return d;
}
__device__ __forceinline__ u64 pk2(float lo, float hi){
    u64 d; asm("mov.b64 %0, {%1, %2};" : "=l"(d) : "f"(lo), "f"(hi)); return d;
}
__device__ __forceinline__ void upk2(u64 v, float& lo, float& hi){
    asm("mov.b64 {%0, %1}, %2;" : "=f"(lo), "=f"(hi) : "l"(v));
}
__device__ __forceinline__ u64 dup2(float f){ return pk2(f, f); }

// full leaky_relu(x) = 0.505*x + 0.495*|x| (slope 0.01) — used only for final h
__device__ __forceinline__ u64 act_lrelu(u64 v){
    u64 av = v & 0x7FFFFFFF7FFFFFFFULL;
    return fma2(av, 0x3EFD70A43EFD70A4ULL /*0.495*/, mul2(v, 0x3F0147AE3F0147AEULL /*0.505*/));
}
// hidden lrelu in g-form: g(x) = x + (0.495/0.505)*|x|; the 0.505 scale is folded
// into the NEXT layer's weights. 1 fma-pipe op instead of 2.
__device__ __forceinline__ u64 act_g(u64 v){
    u64 av = v & 0x7FFFFFFF7FFFFFFFULL;
    return fma2(av, 0x3F7AEE423F7AEE42ULL /*0.98019802*/, v);
}
__device__ __forceinline__ float tanh_ap(float x){
    float r; asm("tanh.approx.f32 %0, %1;" : "=f"(r) : "f"(x)); return r;
}
// hidden sigmoid: PURE tanh. Input x/2 scale folded into producing layer's W,b;
// output affine 0.5t+0.5 folded into next layer's W,b. 0 fma-pipe ops.
__device__ __forceinline__ u64 act_tanh(u64 v){
    float lo, hi; upk2(v, lo, hi);
    return pk2(tanh_ap(lo), tanh_ap(hi));
}
// final-layer sigmoid: near-exact ex2+rcp
__device__ __forceinline__ float fast_sigmoid(float x){
    float e; asm("ex2.approx.f32 %0, %1;" : "=f"(e) : "f"(-1.44269504088896341f * x));
    float r; asm("rcp.approx.f32 %0, %1;" : "=f"(r) : "f"(1.0f + e));
    return r;
}
__device__ __forceinline__ u64 act_sige(u64 v){
    float lo, hi; upk2(v, lo, hi);
    return pk2(fast_sigmoid(lo), fast_sigmoid(hi));
}
// ACT codes: 0 = g-lrelu (hidden h), 1 = tanh (hidden z),
//            2 = exact sigmoid (final z), 3 = full lrelu (final h)
template<int ACT> __device__ __forceinline__ u64 act(u64 v){
    if (ACT == 0) return act_g(v);
    else if (ACT == 1) return act_tanh(v);
    else if (ACT == 2) return act_sige(v);
    else return act_lrelu(v);
}

// scatter one loaded quad into all three items' accumulator pairs
#define SCAT(qv, a0, a1) \
    CA##a0 = fma2(ddA, (qv).x, CA##a0);  CB##a0 = fma2(ddB, (qv).x, CB##a0);  CC##a0 = fma2(ddC, (qv).x, CC##a0); \
    CA##a1 = fma2(ddA, (qv).y, CA##a1);  CB##a1 = fma2(ddB, (qv).y, CB##a1);  CC##a1 = fma2(ddC, (qv).y, CC##a1);

// layer-3 step for one accumulator pair (rows 2i, 2i+1), three items
#define L3STEP(Ci, wlo_idx) { \
    float loA, hiA, loB, hiB, loC, hiC; \
    upk2(CA##Ci, loA, hiA); upk2(CB##Ci, loB, hiB); upk2(CC##Ci, loC, hiC); \
    u64 wl = W3B[wlo_idx], wh = W3B[(wlo_idx)+1]; \
    resA = fma2(dup2(loA), wl, resA);  resB = fma2(dup2(loB), wl, resB);  resC = fma2(dup2(loC), wl, resC); \
    resA = fma2(dup2(hiA), wh, resA);  resB = fma2(dup2(hiB), wh, resB);  resC = fma2(dup2(hiC), wh, resC); }

// one inner iteration body (layer-1 pair p -> scatter into layer-2 accumulators)
#define ITER_BODY { \
    ulonglong2 bw = p1[0]; \
    u64 w1 = ((const u64*)p1)[2]; \
    p1 += 2; \
    u64 axA = fma2(D0A, bw.y, bw.x); axA = fma2(D1A, w1, axA); axA = act<ACT>(axA); \
    u64 axB = fma2(D0B, bw.y, bw.x); axB = fma2(D1B, w1, axB); axB = act<ACT>(axB); \
    u64 axC = fma2(D0C, bw.y, bw.x); axC = fma2(D1C, w1, axC); axC = act<ACT>(axC); \
    float f0A, f1A, f0B, f1B, f0C, f1C; \
    upk2(axA, f0A, f1A); upk2(axB, f0B, f1B); upk2(axC, f0C, f1C); \
    { \
        u64 ddA = dup2(f0A), ddB = dup2(f0B), ddC = dup2(f0C); \
        ulonglong2 q; \
        q = p2[0]; SCAT(q, 0, 1) \
        q = p2[1]; SCAT(q, 2, 3) \
        q = p2[2]; SCAT(q, 4, 5) \
        q = p2[3]; SCAT(q, 6, 7) \
        q = p2[4]; SCAT(q, 8, 9) \
    } \
    { \
        u64 ddA = dup2(f1A), ddB = dup2(f1B), ddC = dup2(f1C); \
        ulonglong2 q; \
        q = p2[5]; SCAT(q, 0, 1) \
        q = p2[6]; SCAT(q, 2, 3) \
        q = p2[7]; SCAT(q, 4, 5) \
        q = p2[8]; SCAT(q, 6, 7) \
        q = p2[9]; SCAT(q, 8, 9) \
    } \
    p2 += 10; }

// ---------- one full 3-layer path, THREE batch items at once ----------
// W1B: 25 pairs x 2 ulonglong2: [ (bias_pair | w_row0_pair), (w_row1_pair | pad) ]
// W2B: [bias: 5 quads][row r: 5 quads each], r = 0..49   (weights pre-folded)
// W3B: [bias pair][row r pair], r = 0..19   (u64 units, pre-folded)
template<int ACT, int ACTF>
__device__ __forceinline__ void path3(const ulonglong2* __restrict__ W1B,
                                      const ulonglong2* __restrict__ W2B,
                                      const u64* __restrict__ W3B,
                                      u64& hA, u64& hB, u64& hC)
{
    float xa0, xa1, xb0, xb1, xc0, xc1;
    upk2(hA, xa0, xa1); upk2(hB, xb0, xb1); upk2(hC, xc0, xc1);
    u64 D0A = dup2(xa0), D1A = dup2(xa1);
    u64 D0B = dup2(xb0), D1B = dup2(xb1);
    u64 D0C = dup2(xc0), D1C = dup2(xc1);

    u64 CA0, CA1, CA2, CA3, CA4, CA5, CA6, CA7, CA8, CA9;
    u64 CB0, CB1, CB2, CB3, CB4, CB5, CB6, CB7, CB8, CB9;
    u64 CC0, CC1, CC2, CC3, CC4, CC5, CC6, CC7, CC8, CC9;
    { ulonglong2 b = W2B[0]; CA0 = b.x; CA1 = b.y; CB0 = b.x; CB1 = b.y; CC0 = b.x; CC1 = b.y; }
    { ulonglong2 b = W2B[1]; CA2 = b.x; CA3 = b.y; CB2 = b.x; CB3 = b.y; CC2 = b.x; CC3 = b.y; }
    { ulonglong2 b = W2B[2]; CA4 = b.x; CA5 = b.y; CB4 = b.x; CB5 = b.y; CC4 = b.x; CC5 = b.y; }
    { ulonglong2 b = W2B[3]; CA6 = b.x; CA7 = b.y; CB6 = b.x; CB7 = b.y; CC6 = b.x; CC7 = b.y; }
    { ulonglong2 b = W2B[4]; CA8 = b.x; CA9 = b.y; CB8 = b.x; CB9 = b.y; CC8 = b.x; CC9 = b.y; }

    const ulonglong2* p1 = W1B;
    const ulonglong2* p2 = W2B + 5;

    #pragma unroll 4
    for (int p = 0; p < 24; p++){
        ITER_BODY
    }
    ITER_BODY

    CA0 = act<ACT>(CA0); CA1 = act<ACT>(CA1); CA2 = act<ACT>(CA2); CA3 = act<ACT>(CA3);
    CA4 = act<ACT>(CA4); CA5 = act<ACT>(CA5); CA6 = act<ACT>(CA6); CA7 = act<ACT>(CA7);
    CA8 = act<ACT>(CA8); CA9 = act<ACT>(CA9);
    CB0 = act<ACT>(CB0); CB1 = act<ACT>(CB1); CB2 = act<ACT>(CB2); CB3 = act<ACT>(CB3);
    CB4 = act<ACT>(CB4); CB5 = act<ACT>(CB5); CB6 = act<ACT>(CB6); CB7 = act<ACT>(CB7);
    CB8 = act<ACT>(CB8); CB9 = act<ACT>(CB9);
    CC0 = act<ACT>(CC0); CC1 = act<ACT>(CC1); CC2 = act<ACT>(CC2); CC3 = act<ACT>(CC3);
    CC4 = act<ACT>(CC4); CC5 = act<ACT>(CC5); CC6 = act<ACT>(CC6); CC7 = act<ACT>(CC7);
    CC8 = act<ACT>(CC8); CC9 = act<ACT>(CC9);

    // layer 3: 20 inputs -> 1 packed output pair, all items
    u64 resA = W3B[0];
    u64 resB = resA;
    u64 resC = resA;
    L3STEP(0,  1)
    L3STEP(1,  3)
    L3STEP(2,  5)
    L3STEP(3,  7)
    L3STEP(4,  9)
    L3STEP(5, 11)
    L3STEP(6, 13)
    L3STEP(7, 15)
    L3STEP(8, 17)
    L3STEP(9, 19)

    hA = act<ACTF>(resA);
    hB = act<ACTF>(resB);
    hC = act<ACTF>(resC);
}

// ---------- shared fills with weight folding (element-wise, no per-thread arrays) ----------
// L1 block: 25 pairs x 8 floats: {b[2p],b[2p+1], W[0][2p],W[0][2p+1], W[1][2p],W[1][2p+1], 0,0}
// all entries scaled: bias*bs, weights*ws
__device__ void fill_L1(float* dstf, const float* __restrict__ W,
                        const float* __restrict__ Bv, float ws, float bs)
{
    for (int e = threadIdx.x; e < 200; e += blockDim.x){
        int p = e >> 3, k = e & 7;
        float v = 0.0f;
        if      (k < 2) v = bs * Bv[2*p + k];
        else if (k < 4) v = ws * W[      2*p + (k-2)];   // row 0 of W[2][50]
        else if (k < 6) v = ws * W[50 +  2*p + (k-4)];   // row 1
        dstf[e] = v;
    }
}
// L2 block (float view): [bias': 20][row r: ws*W], r=0..49
// bias'[j] = bs*b[j] + bc*sum_i W[i][j]
__device__ void fill_L2(float* dstf, const float* __restrict__ W,
                        const float* __restrict__ Bv, float ws, float bs, float bc)
{
    for (int e = threadIdx.x; e < 1020; e += blockDim.x){
        int blk = e / 20, j = e % 20;
        if (blk == 0){
            float cs = 0.0f;
            if (bc != 0.0f)
                for (int i = 0; i < 50; i++) cs += W[i*20 + j];
            dstf[e] = bs * Bv[j] + bc * cs;
        } else {
            dstf[e] = ws * W[(blk - 1) * 20 + j];
        }
    }
}
// L3 block (float view): [b0',b1'][row r: ws*W[2r], ws*W[2r+1]], r=0..19
// bias'[j] = bs*b[j] + bc*sum_i W[i][j]
__device__ void fill_L3(float* dstf, const float* __restrict__ W,
                        const float* __restrict__ Bv, float ws, float bs, float bc)
{
    for (int e = threadIdx.x; e < 42; e += blockDim.x){
        int blk = e >> 1, j = e & 1;
        if (blk == 0){
            float cs = 0.0f;
            if (bc != 0.0f)
                for (int i = 0; i < 20; i++) cs += W[i*2 + j];
            dstf[e] = bs * Bv[j] + bc * cs;
        } else {
            dstf[e] = ws * W[(blk - 1) * 2 + j];
        }
    }
}

// shared layout (ulonglong2 units): H1@0(50)  H2@50(255)  Z1@305(50)  Z2@355(255)
__global__ void __launch_bounds__(128)
recurrent_kernel(const float2* __restrict__ win,
                 const float* __restrict__ Wh1, const float* __restrict__ bh1,
                 const float* __restrict__ Wh2, const float* __restrict__ bh2,
                 const float* __restrict__ Wh3, const float* __restrict__ bh3,
                 const float* __restrict__ Wz1, const float* __restrict__ bz1,
                 const float* __restrict__ Wz2, const float* __restrict__ bz2,
                 const float* __restrict__ Wz3, const float* __restrict__ bz3,
                 float2* __restrict__ out, int Q, int B)
{
    __shared__ ulonglong2 sQ[610];
    __shared__ u64 sP[44];     // H3 @0 (21), Z3 @22 (21)

    const float S = 0.505f;    // lrelu scale folded into next h-layer weights
    // h path: L1 raw (act outputs g(x)); L2/L3 weights carry the 0.505
    fill_L1((float*)(sQ +   0), Wh1, bh1, 1.0f, 1.0f);
    fill_L2((float*)(sQ +  50), Wh2, bh2, S, 1.0f, 0.0f);
    fill_L3((float*)(sP +   0), Wh3, bh3, S, 1.0f, 0.0f);
    // z path: hidden acts are pure tanh.
    //  L1: t1 = tanh(0.5*(W1^T h + b1))          -> W,b scaled 0.5
    //  L2: 0.5*x2 = 0.25*W2^T t1 + 0.5*b2 + 0.25*colsum(W2)
    //  L3: x3 = 0.5*W3^T t2 + b3 + 0.5*colsum(W3); final act exact sigmoid
    fill_L1((float*)(sQ + 305), Wz1, bz1, 0.5f, 0.5f);
    fill_L2((float*)(sQ + 355), Wz2, bz2, 0.25f, 0.5f, 0.25f);
    fill_L3((float*)(sP +  22), Wz3, bz3, 0.5f, 1.0f, 0.5f);
    __syncthreads();

    int tid = blockIdx.x * blockDim.x + threadIdx.x;
    if (tid >= Q) return;

    int idxA = tid;
    int idxB = tid + Q;
    int idxC = tid + 2 * Q;
    bool hasC = (idxC < B);
    int idxCl = hasC ? idxC : (B - 1);

    float2 hinA = win[idxA];
    float2 hinB = win[idxB];
    float2 hinC = win[idxCl];
    u64 hA = pk2(hinA.x, hinA.y);
    u64 hB = pk2(hinB.x, hinB.y);
    u64 hC = pk2(hinC.x, hinC.y);

    float2* opA = out + (size_t)idxA * 19;
    float2* opB = out + (size_t)idxB * 19;
    float2* opC = out + (size_t)idxCl * 19;

    #pragma unroll 1
    for (int t = 0; t < 19; t++){
        // h path: g-lrelu hidden, full lrelu final
        path3<0, 3>(sQ +   0, sQ +  50, sP +  0, hA, hB, hC);
        // z path: tanh hidden (folded), exact sigmoid final
        u64 zA = hA, zB = hB, zC = hC;
        path3<1, 2>(sQ + 305, sQ + 355, sP + 22, zA, zB, zC);
        float lo, hi;
        upk2(zA, lo, hi); opA[t] = make_float2(lo, hi);
        upk2(zB, lo, hi); opB[t] = make_float2(lo, hi);
        if (hasC) { upk2(zC, lo, hi); opC[t] = make_float2(lo, hi); }
    }
}

extern "C" void kernel_launch(void* const* d_in, const int* in_sizes, int n_in,
                              void* d_out, int out_size)
{
    const float* w   = (const float*)d_in[0];
    const float* Wh1 = (const float*)d_in[1];
    const float* bh1 = (const float*)d_in[2];
    const float* Wh2 = (const float*)d_in[3];
    const float* bh2 = (const float*)d_in[4];
    const float* Wh3 = (const float*)d_in[5];
    const float* bh3 = (const float*)d_in[6];
    const float* Wz1 = (const float*)d_in[7];
    const float* bz1 = (const float*)d_in[8];
    const float* Wz2 = (const float*)d_in[9];
    const float* bz2 = (const float*)d_in[10];
    const float* Wz3 = (const float*)d_in[11];
    const float* bz3 = (const float*)d_in[12];

    int B = in_sizes[0] / 2;            // 1048576
    int Q = (B + 2) / 3;
    int threads = 128;
    int blocks = (Q + threads - 1) / threads;
    recurrent_kernel<<<blocks, threads>>>((const float2*)w,
                                          Wh1, bh1, Wh2, bh2, Wh3, bh3,
                                          Wz1, bz1, Wz2, bz2, Wz3, bz3,
                                          (float2*)d_out, Q, B);
}

// round 15
// speedup vs baseline: 1.4956x; 1.0129x over previous
#include <cuda_runtime.h>

typedef unsigned long long u64;

// ---------- packed f32x2 helpers ----------
__device__ __forceinline__ u64 fma2(u64 a, u64 b, u64 c){
    u64 d; asm("fma.rn.f32x2 %0, %1, %2, %3;" : "=l"(d) : "l"(a), "l"(b), "l"(c)); return d;
}
__device__ __forceinline__ u64 mul2(u64 a, u64 b){
    u64 d; asm("mul.rn.f32x2 %0, %1, %2;" : "=l"(d) : "l"(a), "l"(b)); return d;
}
__device__ __forceinline__ u64 pk2(float lo, float hi){
    u64 d; asm("mov.b64 %0, {%1, %2};" : "=l"(d) : "f"(lo), "f"(hi)); return d;
}
__device__ __forceinline__ void upk2(u64 v, float& lo, float& hi){
    asm("mov.b64 {%0, %1}, %2;" : "=f"(lo), "=f"(hi) : "l"(v));
}
__device__ __forceinline__ u64 dup2(float f){ return pk2(f, f); }

// full leaky_relu(x) = 0.505*x + 0.495*|x| (slope 0.01) — used only for final h
__device__ __forceinline__ u64 act_lrelu(u64 v){
    u64 av = v & 0x7FFFFFFF7FFFFFFFULL;
    return fma2(av, 0x3EFD70A43EFD70A4ULL /*0.495*/, mul2(v, 0x3F0147AE3F0147AEULL /*0.505*/));
}
// hidden lrelu in g-form: g(x) = x + (0.495/0.505)*|x|; the 0.505 scale is folded
// into the NEXT layer's weights. 1 fma-pipe op instead of 2.
__device__ __forceinline__ u64 act_g(u64 v){
    u64 av = v & 0x7FFFFFFF7FFFFFFFULL;
    return fma2(av, 0x3F7AEE423F7AEE42ULL /*0.98019802*/, v);
}
__device__ __forceinline__ float tanh_ap(float x){
    float r; asm("tanh.approx.f32 %0, %1;" : "=f"(r) : "f"(x)); return r;
}
// hidden sigmoid: PURE tanh. Input x/2 scale folded into producing layer's W,b;
// output affine 0.5t+0.5 folded into next layer's W,b. 0 fma-pipe ops.
__device__ __forceinline__ u64 act_tanh(u64 v){
    float lo, hi; upk2(v, lo, hi);
    return pk2(tanh_ap(lo), tanh_ap(hi));
}
// final-layer sigmoid: near-exact ex2+rcp
__device__ __forceinline__ float fast_sigmoid(float x){
    float e; asm("ex2.approx.f32 %0, %1;" : "=f"(e) : "f"(-1.44269504088896341f * x));
    float r; asm("rcp.approx.f32 %0, %1;" : "=f"(r) : "f"(1.0f + e));
    return r;
}
__device__ __forceinline__ u64 act_sige(u64 v){
    float lo, hi; upk2(v, lo, hi);
    return pk2(fast_sigmoid(lo), fast_sigmoid(hi));
}
// ACT codes: 0 = g-lrelu (hidden h), 1 = tanh (hidden z),
//            2 = exact sigmoid (final z), 3 = full lrelu (final h)
template<int ACT> __device__ __forceinline__ u64 act(u64 v){
    if (ACT == 0) return act_g(v);
    else if (ACT == 1) return act_tanh(v);
    else if (ACT == 2) return act_sige(v);
    else return act_lrelu(v);
}

// scatter one loaded quad into all three items' accumulator pairs
#define SCAT(qv, a0, a1) \
    CA##a0 = fma2(ddA, (qv).x, CA##a0);  CB##a0 = fma2(ddB, (qv).x, CB##a0);  CC##a0 = fma2(ddC, (qv).x, CC##a0); \
    CA##a1 = fma2(ddA, (qv).y, CA##a1);  CB##a1 = fma2(ddB, (qv).y, CB##a1);  CC##a1 = fma2(ddC, (qv).y, CC##a1);

// layer-3 step for one accumulator pair (rows 2i, 2i+1), three items
#define L3STEP(Ci, wlo_idx) { \
    float loA, hiA, loB, hiB, loC, hiC; \
    upk2(CA##Ci, loA, hiA); upk2(CB##Ci, loB, hiB); upk2(CC##Ci, loC, hiC); \
    u64 wl = W3B[wlo_idx], wh = W3B[(wlo_idx)+1]; \
    resA = fma2(dup2(loA), wl, resA);  resB = fma2(dup2(loB), wl, resB);  resC = fma2(dup2(loC), wl, resC); \
    resA = fma2(dup2(hiA), wh, resA);  resB = fma2(dup2(hiB), wh, resB);  resC = fma2(dup2(hiC), wh, resC); }

// one inner iteration body (layer-1 pair p -> scatter into layer-2 accumulators)
#define ITER_BODY { \
    ulonglong2 bw = p1[0]; \
    u64 w1 = ((const u64*)p1)[2]; \
    p1 += 2; \
    u64 axA = fma2(D0A, bw.y, bw.x); axA = fma2(D1A, w1, axA); axA = act<ACT>(axA); \
    u64 axB = fma2(D0B, bw.y, bw.x); axB = fma2(D1B, w1, axB); axB = act<ACT>(axB); \
    u64 axC = fma2(D0C, bw.y, bw.x); axC = fma2(D1C, w1, axC); axC = act<ACT>(axC); \
    float f0A, f1A, f0B, f1B, f0C, f1C; \
    upk2(axA, f0A, f1A); upk2(axB, f0B, f1B); upk2(axC, f0C, f1C); \
    { \
        u64 ddA = dup2(f0A), ddB = dup2(f0B), ddC = dup2(f0C); \
        ulonglong2 q; \
        q = p2[0]; SCAT(q, 0, 1) \
        q = p2[1]; SCAT(q, 2, 3) \
        q = p2[2]; SCAT(q, 4, 5) \
        q = p2[3]; SCAT(q, 6, 7) \
        q = p2[4]; SCAT(q, 8, 9) \
    } \
    { \
        u64 ddA = dup2(f1A), ddB = dup2(f1B), ddC = dup2(f1C); \
        ulonglong2 q; \
        q = p2[5]; SCAT(q, 0, 1) \
        q = p2[6]; SCAT(q, 2, 3) \
        q = p2[7]; SCAT(q, 4, 5) \
        q = p2[8]; SCAT(q, 6, 7) \
        q = p2[9]; SCAT(q, 8, 9) \
    } \
    p2 += 10; }

// ---------- one full 3-layer path, THREE batch items at once ----------
// W1B: 25 pairs x 2 ulonglong2: [ (bias_pair | w_row0_pair), (w_row1_pair | pad) ]
// W2B: [bias: 5 quads][row r: 5 quads each], r = 0..49   (weights pre-folded)
// W3B: [bias pair][row r pair], r = 0..19   (u64 units, pre-folded)
template<int ACT, int ACTF>
__device__ __forceinline__ void path3(const ulonglong2* __restrict__ W1B,
                                      const ulonglong2* __restrict__ W2B,
                                      const u64* __restrict__ W3B,
                                      u64& hA, u64& hB, u64& hC)
{
    float xa0, xa1, xb0, xb1, xc0, xc1;
    upk2(hA, xa0, xa1); upk2(hB, xb0, xb1); upk2(hC, xc0, xc1);
    u64 D0A = dup2(xa0), D1A = dup2(xa1);
    u64 D0B = dup2(xb0), D1B = dup2(xb1);
    u64 D0C = dup2(xc0), D1C = dup2(xc1);

    u64 CA0, CA1, CA2, CA3, CA4, CA5, CA6, CA7, CA8, CA9;
    u64 CB0, CB1, CB2, CB3, CB4, CB5, CB6, CB7, CB8, CB9;
    u64 CC0, CC1, CC2, CC3, CC4, CC5, CC6, CC7, CC8, CC9;
    { ulonglong2 b = W2B[0]; CA0 = b.x; CA1 = b.y; CB0 = b.x; CB1 = b.y; CC0 = b.x; CC1 = b.y; }
    { ulonglong2 b = W2B[1]; CA2 = b.x; CA3 = b.y; CB2 = b.x; CB3 = b.y; CC2 = b.x; CC3 = b.y; }
    { ulonglong2 b = W2B[2]; CA4 = b.x; CA5 = b.y; CB4 = b.x; CB5 = b.y; CC4 = b.x; CC5 = b.y; }
    { ulonglong2 b = W2B[3]; CA6 = b.x; CA7 = b.y; CB6 = b.x; CB7 = b.y; CC6 = b.x; CC7 = b.y; }
    { ulonglong2 b = W2B[4]; CA8 = b.x; CA9 = b.y; CB8 = b.x; CB9 = b.y; CC8 = b.x; CC9 = b.y; }

    const ulonglong2* p1 = W1B;
    const ulonglong2* p2 = W2B + 5;

    // 24 iterations with an 8-wide scheduling window, then the 25th explicitly.
    #pragma unroll 8
    for (int p = 0; p < 24; p++){
        ITER_BODY
    }
    ITER_BODY

    CA0 = act<ACT>(CA0); CA1 = act<ACT>(CA1); CA2 = act<ACT>(CA2); CA3 = act<ACT>(CA3);
    CA4 = act<ACT>(CA4); CA5 = act<ACT>(CA5); CA6 = act<ACT>(CA6); CA7 = act<ACT>(CA7);
    CA8 = act<ACT>(CA8); CA9 = act<ACT>(CA9);
    CB0 = act<ACT>(CB0); CB1 = act<ACT>(CB1); CB2 = act<ACT>(CB2); CB3 = act<ACT>(CB3);
    CB4 = act<ACT>(CB4); CB5 = act<ACT>(CB5); CB6 = act<ACT>(CB6); CB7 = act<ACT>(CB7);
    CB8 = act<ACT>(CB8); CB9 = act<ACT>(CB9);
    CC0 = act<ACT>(CC0); CC1 = act<ACT>(CC1); CC2 = act<ACT>(CC2); CC3 = act<ACT>(CC3);
    CC4 = act<ACT>(CC4); CC5 = act<ACT>(CC5); CC6 = act<ACT>(CC6); CC7 = act<ACT>(CC7);
    CC8 = act<ACT>(CC8); CC9 = act<ACT>(CC9);

    // layer 3: 20 inputs -> 1 packed output pair, all items
    u64 resA = W3B[0];
    u64 resB = resA;
    u64 resC = resA;
    L3STEP(0,  1)
    L3STEP(1,  3)
    L3STEP(2,  5)
    L3STEP(3,  7)
    L3STEP(4,  9)
    L3STEP(5, 11)
    L3STEP(6, 13)
    L3STEP(7, 15)
    L3STEP(8, 17)
    L3STEP(9, 19)

    hA = act<ACTF>(resA);
    hB = act<ACTF>(resB);
    hC = act<ACTF>(resC);
}

// ---------- shared fills with weight folding (element-wise, no per-thread arrays) ----------
// L1 block: 25 pairs x 8 floats: {b[2p],b[2p+1], W[0][2p],W[0][2p+1], W[1][2p],W[1][2p+1], 0,0}
// all entries scaled: bias*bs, weights*ws
__device__ void fill_L1(float* dstf, const float* __restrict__ W,
                        const float* __restrict__ Bv, float ws, float bs)
{
    for (int e = threadIdx.x; e < 200; e += blockDim.x){
        int p = e >> 3, k = e & 7;
        float v = 0.0f;
        if      (k < 2) v = bs * Bv[2*p + k];
        else if (k < 4) v = ws * W[      2*p + (k-2)];   // row 0 of W[2][50]
        else if (k < 6) v = ws * W[50 +  2*p + (k-4)];   // row 1
        dstf[e] = v;
    }
}
// L2 block (float view): [bias': 20][row r: ws*W], r=0..49
// bias'[j] = bs*b[j] + bc*sum_i W[i][j]
__device__ void fill_L2(float* dstf, const float* __restrict__ W,
                        const float* __restrict__ Bv, float ws, float bs, float bc)
{
    for (int e = threadIdx.x; e < 1020; e += blockDim.x){
        int blk = e / 20, j = e % 20;
        if (blk == 0){
            float cs = 0.0f;
            if (bc != 0.0f)
                for (int i = 0; i < 50; i++) cs += W[i*20 + j];
            dstf[e] = bs * Bv[j] + bc * cs;
        } else {
            dstf[e] = ws * W[(blk - 1) * 20 + j];
        }
    }
}
// L3 block (float view): [b0',b1'][row r: ws*W[2r], ws*W[2r+1]], r=0..19
// bias'[j] = bs*b[j] + bc*sum_i W[i][j]
__device__ void fill_L3(float* dstf, const float* __restrict__ W,
                        const float* __restrict__ Bv, float ws, float bs, float bc)
{
    for (int e = threadIdx.x; e < 42; e += blockDim.x){
        int blk = e >> 1, j = e & 1;
        if (blk == 0){
            float cs = 0.0f;
            if (bc != 0.0f)
                for (int i = 0; i < 20; i++) cs += W[i*2 + j];
            dstf[e] = bs * Bv[j] + bc * cs;
        } else {
            dstf[e] = ws * W[(blk - 1) * 2 + j];
        }
    }
}

// shared layout (ulonglong2 units): H1@0(50)  H2@50(255)  Z1@305(50)  Z2@355(255)
__global__ void __launch_bounds__(128)
recurrent_kernel(const float2* __restrict__ win,
                 const float* __restrict__ Wh1, const float* __restrict__ bh1,
                 const float* __restrict__ Wh2, const float* __restrict__ bh2,
                 const float* __restrict__ Wh3, const float* __restrict__ bh3,
                 const float* __restrict__ Wz1, const float* __restrict__ bz1,
                 const float* __restrict__ Wz2, const float* __restrict__ bz2,
                 const float* __restrict__ Wz3, const float* __restrict__ bz3,
                 float2* __restrict__ out, int Q, int B)
{
    __shared__ ulonglong2 sQ[610];
    __shared__ u64 sP[44];     // H3 @0 (21), Z3 @22 (21)

    const float S = 0.505f;    // lrelu scale folded into next h-layer weights
    fill_L1((float*)(sQ +   0), Wh1, bh1, 1.0f, 1.0f);
    fill_L2((float*)(sQ +  50), Wh2, bh2, S, 1.0f, 0.0f);
    fill_L3((float*)(sP +   0), Wh3, bh3, S, 1.0f, 0.0f);
    fill_L1((float*)(sQ + 305), Wz1, bz1, 0.5f, 0.5f);
    fill_L2((float*)(sQ + 355), Wz2, bz2, 0.25f, 0.5f, 0.25f);
    fill_L3((float*)(sP +  22), Wz3, bz3, 0.5f, 1.0f, 0.5f);
    __syncthreads();

    int tid = blockIdx.x * blockDim.x + threadIdx.x;
    if (tid >= Q) return;

    int idxA = tid;
    int idxB = tid + Q;
    int idxC = tid + 2 * Q;
    bool hasC = (idxC < B);
    int idxCl = hasC ? idxC : (B - 1);

    float2 hinA = win[idxA];
    float2 hinB = win[idxB];
    float2 hinC = win[idxCl];
    u64 hA = pk2(hinA.x, hinA.y);
    u64 hB = pk2(hinB.x, hinB.y);
    u64 hC = pk2(hinC.x, hinC.y);

    float2* opA = out + (size_t)idxA * 19;
    float2* opB = out + (size_t)idxB * 19;
    float2* opC = out + (size_t)idxCl * 19;

    #pragma unroll 1
    for (int t = 0; t < 19; t++){
        // h path: g-lrelu hidden, full lrelu final
        path3<0, 3>(sQ +   0, sQ +  50, sP +  0, hA, hB, hC);
        // z path: tanh hidden (folded), exact sigmoid final
        u64 zA = hA, zB = hB, zC = hC;
        path3<1, 2>(sQ + 305, sQ + 355, sP + 22, zA, zB, zC);
        float lo, hi;
        upk2(zA, lo, hi); opA[t] = make_float2(lo, hi);
        upk2(zB, lo, hi); opB[t] = make_float2(lo, hi);
        if (hasC) { upk2(zC, lo, hi); opC[t] = make_float2(lo, hi); }
    }
}

extern "C" void kernel_launch(void* const* d_in, const int* in_sizes, int n_in,
                              void* d_out, int out_size)
{
    const float* w   = (const float*)d_in[0];
    const float* Wh1 = (const float*)d_in[1];
    const float* bh1 = (const float*)d_in[2];
    const float* Wh2 = (const float*)d_in[3];
    const float* bh2 = (const float*)d_in[4];
    const float* Wh3 = (const float*)d_in[5];
    const float* bh3 = (const float*)d_in[6];
    const float* Wz1 = (const float*)d_in[7];
    const float* bz1 = (const float*)d_in[8];
    const float* Wz2 = (const float*)d_in[9];
    const float* bz2 = (const float*)d_in[10];
    const float* Wz3 = (const float*)d_in[11];
    const float* bz3 = (const float*)d_in[12];

    int B = in_sizes[0] / 2;            // 1048576
    int Q = (B + 2) / 3;
    int threads = 128;
    int blocks = (Q + threads - 1) / threads;
    recurrent_kernel<<<blocks, threads>>>((const float2*)w,
                                          Wh1, bh1, Wh2, bh2, Wh3, bh3,
                                          Wz1, bz1, Wz2, bz2, Wz3, bz3,
                                          (float2*)d_out, Q, B);
}